// round 2
// baseline (speedup 1.0000x reference)
#include <cuda_runtime.h>
#include <math.h>

// ---------------- problem constants ----------------
#define B_    8
#define S_    1024
#define HID_  2048
#define H_    16
#define D_    128
#define M_    (B_*S_)      // 8192 token rows
#define FF_   (4*HID_)     // 8192

// ---------------- scratch (device globals; no allocations allowed) --------
__device__ float g_xn  [(size_t)M_*HID_];   // LN output (reused for LN2)
__device__ float g_q   [(size_t)M_*HID_];
__device__ float g_k   [(size_t)M_*HID_];
__device__ float g_v   [(size_t)M_*HID_];
__device__ float g_qt  [(size_t)M_*HID_];   // [B*H, S, D]
__device__ float g_kt  [(size_t)M_*HID_];
__device__ float g_vt  [(size_t)M_*HID_];
__device__ float g_ctx [(size_t)M_*HID_];   // attention output [B,S,HID]
__device__ float g_acts[(size_t)M_*HID_];   // post-attention residual
__device__ float g_h   [(size_t)M_*FF_];    // FFN hidden (256 MB)

// ---------------- LayerNorm (one block per row, 256 threads) ---------------
__global__ void __launch_bounds__(256) hx_ln(const float* __restrict__ x,
                                             const float* __restrict__ w,
                                             float* __restrict__ out)
{
    const int row = blockIdx.x;
    const int tid = threadIdx.x;
    const float4* xr = (const float4*)(x + (long)row*HID_);
    float4 a = xr[tid];
    float4 b = xr[tid + 256];
    float s  = a.x+a.y+a.z+a.w + b.x+b.y+b.z+b.w;
    float s2 = a.x*a.x+a.y*a.y+a.z*a.z+a.w*a.w
             + b.x*b.x+b.y*b.y+b.z*b.z+b.w*b.w;
#pragma unroll
    for (int o = 16; o; o >>= 1) {
        s  += __shfl_xor_sync(0xffffffffu, s,  o);
        s2 += __shfl_xor_sync(0xffffffffu, s2, o);
    }
    __shared__ float sh[16];
    if ((tid & 31) == 0) { sh[tid >> 5] = s; sh[(tid >> 5) + 8] = s2; }
    __syncthreads();
    float ts = 0.f, ts2 = 0.f;
#pragma unroll
    for (int i = 0; i < 8; i++) { ts += sh[i]; ts2 += sh[i + 8]; }
    const float mean = ts * (1.0f/HID_);
    const float var  = ts2 * (1.0f/HID_) - mean*mean;
    const float rstd = rsqrtf(var + 1e-5f);

    const float4* wr = (const float4*)w;
    float4 w0 = wr[tid], w1v = wr[tid + 256];
    float4 o0, o1;
    o0.x = (a.x-mean)*rstd*w0.x;  o0.y = (a.y-mean)*rstd*w0.y;
    o0.z = (a.z-mean)*rstd*w0.z;  o0.w = (a.w-mean)*rstd*w0.w;
    o1.x = (b.x-mean)*rstd*w1v.x; o1.y = (b.y-mean)*rstd*w1v.y;
    o1.z = (b.z-mean)*rstd*w1v.z; o1.w = (b.w-mean)*rstd*w1v.w;
    float4* orow = (float4*)(out + (long)row*HID_);
    orow[tid] = o0; orow[tid + 256] = o1;
}

// ---------------- SGEMM: C[M,N] = A[M,K] @ B[N,K]^T (+epilogue) ------------
// EPI: 0 = none, 1 = +Res, 2 = exact gelu
template<int EPI>
__global__ void __launch_bounds__(256, 2) hx_sgemm_bt(
    int M, int N, int K,
    const float* __restrict__ A,
    const float* __restrict__ Bm,
    const float* __restrict__ Res,
    float* __restrict__ C)
{
    __shared__ float As[16*132];
    __shared__ float Bs[16*132];
    const int tid = threadIdx.x;
    const int tx = tid & 15;
    const int ty = tid >> 4;
    const int lr = tid >> 2;   // 0..63 (load row)
    const int lc = tid & 3;    // 0..3  (float4 slot within BK=16)
    const long mBase = (long)blockIdx.y * 128;
    const long nBase = (long)blockIdx.x * 128;
    const float* Ag = A  + mBase * K;
    const float* Bg = Bm + nBase * K;

    float acc[8][8];
#pragma unroll
    for (int i = 0; i < 8; i++)
#pragma unroll
        for (int j = 0; j < 8; j++) acc[i][j] = 0.f;

    for (int k0 = 0; k0 < K; k0 += 16) {
#pragma unroll
        for (int p = 0; p < 2; p++) {
            const int r = lr + p*64;
            float4 va = *(const float4*)(Ag + (long)r*K + k0 + lc*4);
            As[(lc*4+0)*132 + r] = va.x;
            As[(lc*4+1)*132 + r] = va.y;
            As[(lc*4+2)*132 + r] = va.z;
            As[(lc*4+3)*132 + r] = va.w;
            float4 vb = *(const float4*)(Bg + (long)r*K + k0 + lc*4);
            Bs[(lc*4+0)*132 + r] = vb.x;
            Bs[(lc*4+1)*132 + r] = vb.y;
            Bs[(lc*4+2)*132 + r] = vb.z;
            Bs[(lc*4+3)*132 + r] = vb.w;
        }
        __syncthreads();
#pragma unroll
        for (int kk = 0; kk < 16; kk++) {
            float rm[8], rn[8];
            *(float4*)&rm[0] = *(const float4*)&As[kk*132 + ty*8];
            *(float4*)&rm[4] = *(const float4*)&As[kk*132 + ty*8 + 4];
            *(float4*)&rn[0] = *(const float4*)&Bs[kk*132 + tx*8];
            *(float4*)&rn[4] = *(const float4*)&Bs[kk*132 + tx*8 + 4];
#pragma unroll
            for (int i = 0; i < 8; i++)
#pragma unroll
                for (int j = 0; j < 8; j++)
                    acc[i][j] = fmaf(rm[i], rn[j], acc[i][j]);
        }
        __syncthreads();
    }
#pragma unroll
    for (int i = 0; i < 8; i++) {
        const long row = mBase + ty*8 + i;
        const long off = row*N + nBase + tx*8;
#pragma unroll
        for (int j = 0; j < 8; j++) {
            float v = acc[i][j];
            if (EPI == 1) v += Res[off + j];
            if (EPI == 2) v = 0.5f*v*(1.0f + erff(v*0.70710678118654752f));
            C[off + j] = v;
        }
    }
}

// ---------------- xPos rotary on K,V + transpose Q/K/V to [B*H,S,D] --------
__global__ void hx_rope(const float* __restrict__ q, const float* __restrict__ k,
                        const float* __restrict__ v, const int* __restrict__ pidx,
                        float* __restrict__ qt, float* __restrict__ kt,
                        float* __restrict__ vt)
{
    const long gid = (long)blockIdx.x * blockDim.x + threadIdx.x;
    const long total = (long)M_ * H_ * (D_/2);
    if (gid >= total) return;
    const int  i  = (int)(gid & 63);          // dim-pair index
    const int  h  = (int)((gid >> 6) & (H_-1));
    const long bs = gid >> 10;                // b*S + s
    const int  s  = (int)(bs & (S_-1));
    const int  b  = (int)(bs >> 10);

    const long in_off  = bs*HID_ + h*D_ + 2*i;
    const long out_off = (((long)(b*H_ + h))*S_ + s)*D_ + 2*i;

    float2 qq = *(const float2*)(q + in_off);
    float2 kk = *(const float2*)(k + in_off);
    float2 vv = *(const float2*)(v + in_off);

    const float seq = (float)(pidx[0] + s - (S_/2)) * (1.0f/512.0f);
    const float df  = 2.0f * (float)(i + 1);                 // drange
    const float theta = expf(-(df * (1.0f/(float)D_)) * 9.210340371976184f); // ln(1e4)
    float sn, c;
    sincosf(seq * theta, &sn, &c);
    const float zeta = (df*(1.0f/64.0f) + 51.2f) * (1.0f/52.2f);
    const float t  = powf(zeta, seq);
    const float it = 1.0f / t;

    float2 ko, vo;
    ko.x = (kk.x*c - kk.y*sn)*t;   ko.y = (kk.y*c + kk.x*sn)*t;
    vo.x = (vv.x*c - vv.y*sn)*it;  vo.y = (vv.y*c + vv.x*sn)*it;

    *(float2*)(qt + out_off) = qq;
    *(float2*)(kt + out_off) = ko;
    *(float2*)(vt + out_off) = vo;
}

// ---------------- causal flash attention (fp32, BM=BN=64, D=128) -----------
#define ATTN_SMEM_FLOATS (128*65 + 128*65 + 64*65 + 64*128)
__global__ void __launch_bounds__(256) hx_attn(
    const float* __restrict__ qt, const float* __restrict__ kt,
    const float* __restrict__ vt, float* __restrict__ ctx)
{
    extern __shared__ float sm[];
    float* Qst = sm;                 // [128][65]  (Q transposed: [d][m])
    float* Kst = Qst + 128*65;       // [128][65]  ([d][n])
    float* Pst = Kst + 128*65;       // [64][65]   ([n][m])
    float* Vs  = Pst + 64*65;        // [64][128]  ([n][c])

    const int qtile = blockIdx.x;
    const int bh    = blockIdx.y;
    const int b = bh >> 4, h = bh & 15;
    const float* Qg = qt + ((long)bh*S_ + qtile*64)*D_;
    const float* Kg = kt + (long)bh*S_*D_;
    const float* Vg = vt + (long)bh*S_*D_;

    const int tid = threadIdx.x;
    const int d4 = tid & 31, mr = tid >> 5;
    const int tx = tid & 15, ty = tid >> 4;

#pragma unroll
    for (int p = 0; p < 8; p++) {
        const int m = mr + p*8;
        float4 qv = *(const float4*)(Qg + m*D_ + d4*4);
        Qst[(d4*4+0)*65 + m] = qv.x;
        Qst[(d4*4+1)*65 + m] = qv.y;
        Qst[(d4*4+2)*65 + m] = qv.z;
        Qst[(d4*4+3)*65 + m] = qv.w;
    }

    float mi[4], li[4], o[4][8];
#pragma unroll
    for (int i = 0; i < 4; i++) {
        mi[i] = -INFINITY; li[i] = 0.f;
#pragma unroll
        for (int c = 0; c < 8; c++) o[i][c] = 0.f;
    }
    const float scale = 0.088388347648318447f; // 1/sqrt(128)

    for (int j = 0; j <= qtile; j++) {
        __syncthreads();  // prior iter readers done (also guards first Qst use)
#pragma unroll
        for (int p = 0; p < 8; p++) {
            const int n = mr + p*8;
            float4 kv = *(const float4*)(Kg + (long)(j*64 + n)*D_ + d4*4);
            Kst[(d4*4+0)*65 + n] = kv.x;
            Kst[(d4*4+1)*65 + n] = kv.y;
            Kst[(d4*4+2)*65 + n] = kv.z;
            Kst[(d4*4+3)*65 + n] = kv.w;
            float4 vv = *(const float4*)(Vg + (long)(j*64 + n)*D_ + d4*4);
            *(float4*)&Vs[n*128 + d4*4] = vv;
        }
        __syncthreads();

        // S = Q K^T (each thread: 4x4 scores)
        float sacc[4][4];
#pragma unroll
        for (int i = 0; i < 4; i++)
#pragma unroll
            for (int jj = 0; jj < 4; jj++) sacc[i][jj] = 0.f;
        for (int d = 0; d < 128; d++) {
            float qr[4], kr[4];
#pragma unroll
            for (int i = 0; i < 4; i++)  qr[i]  = Qst[d*65 + ty*4 + i];
#pragma unroll
            for (int jj = 0; jj < 4; jj++) kr[jj] = Kst[d*65 + tx*4 + jj];
#pragma unroll
            for (int i = 0; i < 4; i++)
#pragma unroll
                for (int jj = 0; jj < 4; jj++)
                    sacc[i][jj] = fmaf(qr[i], kr[jj], sacc[i][jj]);
        }

        // online softmax per owned row
#pragma unroll
        for (int i = 0; i < 4; i++) {
            const int mg = qtile*64 + ty*4 + i;
            float rmax = -INFINITY;
#pragma unroll
            for (int jj = 0; jj < 4; jj++) {
                const int ng = j*64 + tx*4 + jj;
                float sv = sacc[i][jj] * scale;
                sv = (ng <= mg) ? sv : -INFINITY;
                sacc[i][jj] = sv;
                rmax = fmaxf(rmax, sv);
            }
#pragma unroll
            for (int off = 8; off; off >>= 1)
                rmax = fmaxf(rmax, __shfl_xor_sync(0xffffffffu, rmax, off));
            const float mnew  = fmaxf(mi[i], rmax);
            const float alpha = expf(mi[i] - mnew);
            float rsum = 0.f;
#pragma unroll
            for (int jj = 0; jj < 4; jj++) {
                const float pv = expf(sacc[i][jj] - mnew);
                sacc[i][jj] = pv;
                rsum += pv;
            }
#pragma unroll
            for (int off = 8; off; off >>= 1)
                rsum += __shfl_xor_sync(0xffffffffu, rsum, off);
            li[i] = li[i]*alpha + rsum;
            mi[i] = mnew;
#pragma unroll
            for (int c = 0; c < 8; c++) o[i][c] *= alpha;
#pragma unroll
            for (int jj = 0; jj < 4; jj++)
                Pst[(tx*4 + jj)*65 + ty*4 + i] = sacc[i][jj];
        }
        __syncthreads();

        // O += P V  (each thread: 4 rows x 8 cols)
#pragma unroll 4
        for (int n = 0; n < 64; n++) {
            float pr[4], vr[8];
#pragma unroll
            for (int i = 0; i < 4; i++) pr[i] = Pst[n*65 + ty*4 + i];
#pragma unroll
            for (int c = 0; c < 8; c++) vr[c] = Vs[n*128 + tx*8 + c];
#pragma unroll
            for (int i = 0; i < 4; i++)
#pragma unroll
                for (int c = 0; c < 8; c++)
                    o[i][c] = fmaf(pr[i], vr[c], o[i][c]);
        }
    }

    // write ctx in [B,S,HID] layout
#pragma unroll
    for (int i = 0; i < 4; i++) {
        const float inv = 1.0f / li[i];
        const int sq = qtile*64 + ty*4 + i;
        const long off = ((long)(b*S_ + sq))*HID_ + h*D_ + tx*8;
#pragma unroll
        for (int c = 0; c < 8; c++)
            ctx[off + c] = o[i][c]*inv;
    }
}

// ---------------- launch ----------------------------------------------------
extern "C" void kernel_launch(void* const* d_in, const int* in_sizes, int n_in,
                              void* d_out, int out_size)
{
    const float* acts_in = (const float*)d_in[0];
    const float* ln1_w   = (const float*)d_in[4];
    const float* ln2_w   = (const float*)d_in[5];
    const float* q_w     = (const float*)d_in[6];
    const float* k_w     = (const float*)d_in[7];
    const float* v_w     = (const float*)d_in[8];
    const float* o_w     = (const float*)d_in[9];
    const float* w1      = (const float*)d_in[10];
    const float* w2      = (const float*)d_in[11];
    const int*   p_index = (const int*)d_in[3];
    float* out = (float*)d_out;

    float *p_xn, *p_q, *p_k, *p_v, *p_qt, *p_kt, *p_vt, *p_ctx, *p_acts, *p_h;
    cudaGetSymbolAddress((void**)&p_xn,  g_xn);
    cudaGetSymbolAddress((void**)&p_q,   g_q);
    cudaGetSymbolAddress((void**)&p_k,   g_k);
    cudaGetSymbolAddress((void**)&p_v,   g_v);
    cudaGetSymbolAddress((void**)&p_qt,  g_qt);
    cudaGetSymbolAddress((void**)&p_kt,  g_kt);
    cudaGetSymbolAddress((void**)&p_vt,  g_vt);
    cudaGetSymbolAddress((void**)&p_ctx, g_ctx);
    cudaGetSymbolAddress((void**)&p_acts,g_acts);
    cudaGetSymbolAddress((void**)&p_h,   g_h);

    // 1) LN1
    hx_ln<<<M_, 256>>>(acts_in, ln1_w, p_xn);

    // 2) QKV projections
    dim3 gQ(HID_/128, M_/128);
    hx_sgemm_bt<0><<<gQ, 256>>>(M_, HID_, HID_, p_xn, q_w, nullptr, p_q);
    hx_sgemm_bt<0><<<gQ, 256>>>(M_, HID_, HID_, p_xn, k_w, nullptr, p_k);
    hx_sgemm_bt<0><<<gQ, 256>>>(M_, HID_, HID_, p_xn, v_w, nullptr, p_v);

    // 3) xPos rotary (K,V) + transpose all to [B*H, S, D]
    const long nrope = (long)M_*H_*(D_/2);
    hx_rope<<<(unsigned)((nrope + 255)/256), 256>>>(p_q, p_k, p_v, p_index,
                                                    p_qt, p_kt, p_vt);

    // 4) causal flash attention
    const int attn_smem = ATTN_SMEM_FLOATS * (int)sizeof(float);
    cudaFuncSetAttribute(hx_attn, cudaFuncAttributeMaxDynamicSharedMemorySize,
                         attn_smem);
    hx_attn<<<dim3(S_/64, B_*H_), 256, attn_smem>>>(p_qt, p_kt, p_vt, p_ctx);

    // 5) O projection + residual
    hx_sgemm_bt<1><<<gQ, 256>>>(M_, HID_, HID_, p_ctx, o_w, acts_in, p_acts);

    // 6) LN2
    hx_ln<<<M_, 256>>>(p_acts, ln2_w, p_xn);

    // 7) FFN up + exact GELU
    dim3 gF(FF_/128, M_/128);
    hx_sgemm_bt<2><<<gF, 256>>>(M_, FF_, HID_, p_xn, w1, nullptr, p_h);

    // 8) FFN down + residual -> output acts
    hx_sgemm_bt<1><<<gQ, 256>>>(M_, HID_, FF_, p_h, w2, p_acts, out);

    // 9) pass-through caches (returned unchanged by reference)
    const long actN = (long)M_*HID_;
    if (n_in > 2 && (long)out_size >= actN + (long)in_sizes[1] + (long)in_sizes[2]) {
        cudaMemcpyAsync(out + actN, d_in[1],
                        (size_t)in_sizes[1]*sizeof(float),
                        cudaMemcpyDeviceToDevice);
        cudaMemcpyAsync(out + actN + in_sizes[1], d_in[2],
                        (size_t)in_sizes[2]*sizeof(float),
                        cudaMemcpyDeviceToDevice);
    }
}

// round 4
// speedup vs baseline: 1.8799x; 1.8799x over previous
#include <cuda_runtime.h>
#include <cuda_bf16.h>
#include <cstdint>
#include <math.h>

// ---------------- problem constants ----------------
#define B_    8
#define S_    1024
#define HID_  2048
#define H_    16
#define D_    128
#define M_    (B_*S_)      // 8192 token rows
#define FF_   (4*HID_)     // 8192

// ---------------- scratch (device globals; no allocations allowed) --------
__device__ float g_xn  [(size_t)M_*HID_];
__device__ float g_q   [(size_t)M_*HID_];
__device__ float g_k   [(size_t)M_*HID_];
__device__ float g_v   [(size_t)M_*HID_];
__device__ float g_qt  [(size_t)M_*HID_];
__device__ float g_kt  [(size_t)M_*HID_];
__device__ float g_vt  [(size_t)M_*HID_];
__device__ float g_ctx [(size_t)M_*HID_];
__device__ float g_acts[(size_t)M_*HID_];
__device__ float g_h   [(size_t)M_*FF_];

// ---------------- helpers ---------------------------------------------------
__device__ __forceinline__ uint32_t hx_smem_u32(const void* p) {
    uint32_t a;
    asm("{ .reg .u64 t; cvta.to.shared.u64 t, %1; cvt.u32.u64 %0, t; }" : "=r"(a) : "l"(p));
    return a;
}
#define HX_LDSM4(r, addr) \
    asm volatile("ldmatrix.sync.aligned.m8n8.x4.shared.b16 {%0,%1,%2,%3}, [%4];" \
        : "=r"((r)[0]), "=r"((r)[1]), "=r"((r)[2]), "=r"((r)[3]) : "r"(addr))

#define HX_MMA(d, a, b0, b1) \
    asm volatile("mma.sync.aligned.m16n8k16.row.col.f32.bf16.bf16.f32 " \
        "{%0,%1,%2,%3}, {%4,%5,%6,%7}, {%8,%9}, {%0,%1,%2,%3};" \
        : "+f"((d)[0]), "+f"((d)[1]), "+f"((d)[2]), "+f"((d)[3]) \
        : "r"((a)[0]), "r"((a)[1]), "r"((a)[2]), "r"((a)[3]), "r"(b0), "r"(b1))

__device__ __forceinline__ uint32_t hx_pk(__nv_bfloat16 a, __nv_bfloat16 b) {
    __nv_bfloat162 t; t.x = a; t.y = b;
    return *(uint32_t*)&t;
}
// split 8 fp32 (two float4) into hi-bf16 (uint4) and lo-bf16 (uint4)
__device__ __forceinline__ void hx_split8(float4 v0, float4 v1, uint4& h, uint4& l) {
    __nv_bfloat16 h0 = __float2bfloat16(v0.x), h1 = __float2bfloat16(v0.y);
    __nv_bfloat16 h2 = __float2bfloat16(v0.z), h3 = __float2bfloat16(v0.w);
    __nv_bfloat16 h4 = __float2bfloat16(v1.x), h5 = __float2bfloat16(v1.y);
    __nv_bfloat16 h6 = __float2bfloat16(v1.z), h7 = __float2bfloat16(v1.w);
    h.x = hx_pk(h0, h1); h.y = hx_pk(h2, h3);
    h.z = hx_pk(h4, h5); h.w = hx_pk(h6, h7);
    l.x = hx_pk(__float2bfloat16(v0.x - __bfloat162float(h0)),
                __float2bfloat16(v0.y - __bfloat162float(h1)));
    l.y = hx_pk(__float2bfloat16(v0.z - __bfloat162float(h2)),
                __float2bfloat16(v0.w - __bfloat162float(h3)));
    l.z = hx_pk(__float2bfloat16(v1.x - __bfloat162float(h4)),
                __float2bfloat16(v1.y - __bfloat162float(h5)));
    l.w = hx_pk(__float2bfloat16(v1.z - __bfloat162float(h6)),
                __float2bfloat16(v1.w - __bfloat162float(h7)));
}

// ---------------- split-bf16 tensor-core GEMM (mma.sync, base ISA) ----------
// C[M,N] = A[M,K] @ B[N,K]^T, fp32 in/out.
// CTA 128x128, K-chunk 32, 8 warps (2m x 4n), warp tile 64x32.
// SMEM stage: Ah/Al/Bh/Bl, each 128 rows x 80B (64B data + 16B pad). 2 stages.
// EPI: 0 = none, 1 = +Res, 2 = exact gelu
#define MMG_STAGE   40960
#define MMG_SMEM    (2*MMG_STAGE)

template<int EPI>
__global__ void __launch_bounds__(256, 1) mm_gemm(
    int M, int N, int K,
    const float* __restrict__ A,
    const float* __restrict__ Bm,
    const float* __restrict__ Res,
    float* __restrict__ C,
    int tiles_n)
{
    extern __shared__ char smc[];
    const uint32_t smb = hx_smem_u32(smc);
    const int tid  = threadIdx.x;
    const int lane = tid & 31;
    const int warp = tid >> 5;
    const int wm = warp & 1;     // 0..1 -> m offset wm*64
    const int wn = warp >> 1;    // 0..3 -> n offset wn*32

    // supertile raster: 16 m-tiles per band to keep wave working set in L2
    const int SUPER = 16;
    const int per  = SUPER * tiles_n;
    const int band = blockIdx.x / per;
    const int rem  = blockIdx.x % per;
    const int mt = band * SUPER + (rem % SUPER);
    const int nt = rem / SUPER;

    const float* Ag = A  + (long)mt * 128 * K;
    const float* Bg = Bm + (long)nt * 128 * K;

    float acc[4][4][4];
#pragma unroll
    for (int i = 0; i < 4; i++)
#pragma unroll
        for (int j = 0; j < 4; j++)
#pragma unroll
            for (int r = 0; r < 4; r++) acc[i][j][r] = 0.f;

    const int row_ld = tid >> 2;        // 0..63 base row (plus 64 for p=1)
    const int seg_ld = tid & 3;         // 16B segment within 64B row

    float4 buf[8];
    auto ldg = [&](int c) {
#pragma unroll
        for (int p = 0; p < 2; p++) {
            const int row = row_ld + p * 64;
            const float4* a = (const float4*)(Ag + (long)row * K + c * 32 + seg_ld * 8);
            buf[p*2]   = a[0];
            buf[p*2+1] = a[1];
            const float4* b = (const float4*)(Bg + (long)row * K + c * 32 + seg_ld * 8);
            buf[4+p*2]   = b[0];
            buf[4+p*2+1] = b[1];
        }
    };
    auto sts = [&](int st) {
        char* stb = smc + st * MMG_STAGE;
#pragma unroll
        for (int p = 0; p < 2; p++) {
            const int row = row_ld + p * 64;
            const uint32_t o = row * 80 + seg_ld * 16;
            uint4 h, l;
            hx_split8(buf[p*2], buf[p*2+1], h, l);
            *(uint4*)(stb + o)         = h;
            *(uint4*)(stb + 10240 + o) = l;
            hx_split8(buf[4+p*2], buf[4+p*2+1], h, l);
            *(uint4*)(stb + 20480 + o) = h;
            *(uint4*)(stb + 30720 + o) = l;
        }
    };

    const int nch = K / 32;
    ldg(0);
    sts(0);

    for (int c = 0; c < nch; c++) {
        const int st = c & 1;
        __syncthreads();                 // stage st of chunk c visible; prev compute done
        if (c + 1 < nch) ldg(c + 1);

        const uint32_t stb = smb + st * MMG_STAGE;
#pragma unroll
        for (int ks = 0; ks < 2; ks++) {
            const uint32_t colb = (ks * 16 + (lane >> 4) * 8) * 2;
            uint32_t ah[4][4], al[4][4], bh[2][4], bl[2][4];
#pragma unroll
            for (int im = 0; im < 4; im++) {
                const uint32_t row = wm * 64 + im * 16 + (lane & 15);
                const uint32_t ad = stb + row * 80 + colb;
                HX_LDSM4(ah[im], ad);
                HX_LDSM4(al[im], ad + 10240);
            }
#pragma unroll
            for (int ib = 0; ib < 2; ib++) {
                const uint32_t row = wn * 32 + ib * 16 + (lane & 15);
                const uint32_t bd = stb + 20480 + row * 80 + colb;
                HX_LDSM4(bh[ib], bd);
                HX_LDSM4(bl[ib], bd + 10240);
            }
#pragma unroll
            for (int im = 0; im < 4; im++)
#pragma unroll
                for (int j = 0; j < 4; j++) {
                    const int ib = j >> 1, t = j & 1;
                    HX_MMA(acc[im][j], ah[im], bh[ib][t], bh[ib][t+2]); // hh
                    HX_MMA(acc[im][j], ah[im], bl[ib][t], bl[ib][t+2]); // hl
                    HX_MMA(acc[im][j], al[im], bh[ib][t], bh[ib][t+2]); // lh
                }
        }
        if (c + 1 < nch) sts((c + 1) & 1);
    }

    // ---- epilogue: registers -> global fp32 ----
#pragma unroll
    for (int im = 0; im < 4; im++)
#pragma unroll
        for (int j = 0; j < 4; j++) {
            const long row0 = (long)mt * 128 + wm * 64 + im * 16 + (lane >> 2);
            const long col  = (long)nt * 128 + wn * 32 + j * 8 + (lane & 3) * 2;
            const long o0 = row0 * N + col;
            const long o1 = (row0 + 8) * N + col;
            float2 v0 = { acc[im][j][0], acc[im][j][1] };
            float2 v1 = { acc[im][j][2], acc[im][j][3] };
            if (EPI == 1) {
                const float2 r0 = *(const float2*)(Res + o0);
                const float2 r1 = *(const float2*)(Res + o1);
                v0.x += r0.x; v0.y += r0.y; v1.x += r1.x; v1.y += r1.y;
            }
            if (EPI == 2) {
                v0.x = 0.5f*v0.x*(1.0f + erff(v0.x*0.70710678118654752f));
                v0.y = 0.5f*v0.y*(1.0f + erff(v0.y*0.70710678118654752f));
                v1.x = 0.5f*v1.x*(1.0f + erff(v1.x*0.70710678118654752f));
                v1.y = 0.5f*v1.y*(1.0f + erff(v1.y*0.70710678118654752f));
            }
            *(float2*)(C + o0) = v0;
            *(float2*)(C + o1) = v1;
        }
}

// ---------------- LayerNorm (one block per row, 256 threads) ---------------
__global__ void __launch_bounds__(256) hx_ln(const float* __restrict__ x,
                                             const float* __restrict__ w,
                                             float* __restrict__ out)
{
    const int row = blockIdx.x;
    const int tid = threadIdx.x;
    const float4* xr = (const float4*)(x + (long)row*HID_);
    float4 a = xr[tid];
    float4 b = xr[tid + 256];
    float s  = a.x+a.y+a.z+a.w + b.x+b.y+b.z+b.w;
    float s2 = a.x*a.x+a.y*a.y+a.z*a.z+a.w*a.w
             + b.x*b.x+b.y*b.y+b.z*b.z+b.w*b.w;
#pragma unroll
    for (int o = 16; o; o >>= 1) {
        s  += __shfl_xor_sync(0xffffffffu, s,  o);
        s2 += __shfl_xor_sync(0xffffffffu, s2, o);
    }
    __shared__ float sh[16];
    if ((tid & 31) == 0) { sh[tid >> 5] = s; sh[(tid >> 5) + 8] = s2; }
    __syncthreads();
    float ts = 0.f, ts2 = 0.f;
#pragma unroll
    for (int i = 0; i < 8; i++) { ts += sh[i]; ts2 += sh[i + 8]; }
    const float mean = ts * (1.0f/HID_);
    const float var  = ts2 * (1.0f/HID_) - mean*mean;
    const float rstd = rsqrtf(var + 1e-5f);

    const float4* wr = (const float4*)w;
    float4 w0 = wr[tid], w1v = wr[tid + 256];
    float4 o0, o1;
    o0.x = (a.x-mean)*rstd*w0.x;  o0.y = (a.y-mean)*rstd*w0.y;
    o0.z = (a.z-mean)*rstd*w0.z;  o0.w = (a.w-mean)*rstd*w0.w;
    o1.x = (b.x-mean)*rstd*w1v.x; o1.y = (b.y-mean)*rstd*w1v.y;
    o1.z = (b.z-mean)*rstd*w1v.z; o1.w = (b.w-mean)*rstd*w1v.w;
    float4* orow = (float4*)(out + (long)row*HID_);
    orow[tid] = o0; orow[tid + 256] = o1;
}

// ---------------- xPos rotary on K,V + transpose Q/K/V to [B*H,S,D] --------
__global__ void hx_rope(const float* __restrict__ q, const float* __restrict__ k,
                        const float* __restrict__ v, const int* __restrict__ pidx,
                        float* __restrict__ qt, float* __restrict__ kt,
                        float* __restrict__ vt)
{
    const long gid = (long)blockIdx.x * blockDim.x + threadIdx.x;
    const long total = (long)M_ * H_ * (D_/2);
    if (gid >= total) return;
    const int  i  = (int)(gid & 63);
    const int  h  = (int)((gid >> 6) & (H_-1));
    const long bs = gid >> 10;
    const int  s  = (int)(bs & (S_-1));
    const int  b  = (int)(bs >> 10);

    const long in_off  = bs*HID_ + h*D_ + 2*i;
    const long out_off = (((long)(b*H_ + h))*S_ + s)*D_ + 2*i;

    float2 qq = *(const float2*)(q + in_off);
    float2 kk = *(const float2*)(k + in_off);
    float2 vv = *(const float2*)(v + in_off);

    const float seq = (float)(pidx[0] + s - (S_/2)) * (1.0f/512.0f);
    const float df  = 2.0f * (float)(i + 1);
    const float theta = expf(-(df * (1.0f/(float)D_)) * 9.210340371976184f);
    float sn, c;
    sincosf(seq * theta, &sn, &c);
    const float zeta = (df*(1.0f/64.0f) + 51.2f) * (1.0f/52.2f);
    const float t  = powf(zeta, seq);
    const float it = 1.0f / t;

    float2 ko, vo;
    ko.x = (kk.x*c - kk.y*sn)*t;   ko.y = (kk.y*c + kk.x*sn)*t;
    vo.x = (vv.x*c - vv.y*sn)*it;  vo.y = (vv.y*c + vv.x*sn)*it;

    *(float2*)(qt + out_off) = qq;
    *(float2*)(kt + out_off) = ko;
    *(float2*)(vt + out_off) = vo;
}

// ---------------- causal flash attention (fp32, BM=BN=64, D=128) -----------
#define ATTN_SMEM_FLOATS (128*65 + 128*65 + 64*65 + 64*128)
__global__ void __launch_bounds__(256) hx_attn(
    const float* __restrict__ qt, const float* __restrict__ kt,
    const float* __restrict__ vt, float* __restrict__ ctx)
{
    extern __shared__ float smf[];
    float* Qst = smf;
    float* Kst = Qst + 128*65;
    float* Pst = Kst + 128*65;
    float* Vs  = Pst + 64*65;

    const int qtile = blockIdx.x;
    const int bh    = blockIdx.y;
    const int b = bh >> 4, h = bh & 15;
    const float* Qg = qt + ((long)bh*S_ + qtile*64)*D_;
    const float* Kg = kt + (long)bh*S_*D_;
    const float* Vg = vt + (long)bh*S_*D_;

    const int tid = threadIdx.x;
    const int d4 = tid & 31, mr = tid >> 5;
    const int tx = tid & 15, ty = tid >> 4;

#pragma unroll
    for (int p = 0; p < 8; p++) {
        const int m = mr + p*8;
        float4 qv = *(const float4*)(Qg + m*D_ + d4*4);
        Qst[(d4*4+0)*65 + m] = qv.x;
        Qst[(d4*4+1)*65 + m] = qv.y;
        Qst[(d4*4+2)*65 + m] = qv.z;
        Qst[(d4*4+3)*65 + m] = qv.w;
    }

    float mi[4], li[4], o[4][8];
#pragma unroll
    for (int i = 0; i < 4; i++) {
        mi[i] = -INFINITY; li[i] = 0.f;
#pragma unroll
        for (int c = 0; c < 8; c++) o[i][c] = 0.f;
    }
    const float scale = 0.088388347648318447f;

    for (int j = 0; j <= qtile; j++) {
        __syncthreads();
#pragma unroll
        for (int p = 0; p < 8; p++) {
            const int n = mr + p*8;
            float4 kv = *(const float4*)(Kg + (long)(j*64 + n)*D_ + d4*4);
            Kst[(d4*4+0)*65 + n] = kv.x;
            Kst[(d4*4+1)*65 + n] = kv.y;
            Kst[(d4*4+2)*65 + n] = kv.z;
            Kst[(d4*4+3)*65 + n] = kv.w;
            float4 vv = *(const float4*)(Vg + (long)(j*64 + n)*D_ + d4*4);
            *(float4*)&Vs[n*128 + d4*4] = vv;
        }
        __syncthreads();

        float sacc[4][4];
#pragma unroll
        for (int i = 0; i < 4; i++)
#pragma unroll
            for (int jj = 0; jj < 4; jj++) sacc[i][jj] = 0.f;
        for (int d = 0; d < 128; d++) {
            float qr[4], kr[4];
#pragma unroll
            for (int i = 0; i < 4; i++)  qr[i]  = Qst[d*65 + ty*4 + i];
#pragma unroll
            for (int jj = 0; jj < 4; jj++) kr[jj] = Kst[d*65 + tx*4 + jj];
#pragma unroll
            for (int i = 0; i < 4; i++)
#pragma unroll
                for (int jj = 0; jj < 4; jj++)
                    sacc[i][jj] = fmaf(qr[i], kr[jj], sacc[i][jj]);
        }

#pragma unroll
        for (int i = 0; i < 4; i++) {
            const int mg = qtile*64 + ty*4 + i;
            float rmax = -INFINITY;
#pragma unroll
            for (int jj = 0; jj < 4; jj++) {
                const int ng = j*64 + tx*4 + jj;
                float sv = sacc[i][jj] * scale;
                sv = (ng <= mg) ? sv : -INFINITY;
                sacc[i][jj] = sv;
                rmax = fmaxf(rmax, sv);
            }
#pragma unroll
            for (int off = 8; off; off >>= 1)
                rmax = fmaxf(rmax, __shfl_xor_sync(0xffffffffu, rmax, off));
            const float mnew  = fmaxf(mi[i], rmax);
            const float alpha = expf(mi[i] - mnew);
            float rsum = 0.f;
#pragma unroll
            for (int jj = 0; jj < 4; jj++) {
                const float pv = expf(sacc[i][jj] - mnew);
                sacc[i][jj] = pv;
                rsum += pv;
            }
#pragma unroll
            for (int off = 8; off; off >>= 1)
                rsum += __shfl_xor_sync(0xffffffffu, rsum, off);
            li[i] = li[i]*alpha + rsum;
            mi[i] = mnew;
#pragma unroll
            for (int c = 0; c < 8; c++) o[i][c] *= alpha;
#pragma unroll
            for (int jj = 0; jj < 4; jj++)
                Pst[(tx*4 + jj)*65 + ty*4 + i] = sacc[i][jj];
        }
        __syncthreads();

#pragma unroll 4
        for (int n = 0; n < 64; n++) {
            float pr[4], vr[8];
#pragma unroll
            for (int i = 0; i < 4; i++) pr[i] = Pst[n*65 + ty*4 + i];
#pragma unroll
            for (int c = 0; c < 8; c++) vr[c] = Vs[n*128 + tx*8 + c];
#pragma unroll
            for (int i = 0; i < 4; i++)
#pragma unroll
                for (int c = 0; c < 8; c++)
                    o[i][c] = fmaf(pr[i], vr[c], o[i][c]);
        }
    }

#pragma unroll
    for (int i = 0; i < 4; i++) {
        const float inv = 1.0f / li[i];
        const int sq = qtile*64 + ty*4 + i;
        const long off = ((long)(b*S_ + sq))*HID_ + h*D_ + tx*8;
#pragma unroll
        for (int c = 0; c < 8; c++)
            ctx[off + c] = o[i][c]*inv;
    }
}

// ---------------- launch ----------------------------------------------------
extern "C" void kernel_launch(void* const* d_in, const int* in_sizes, int n_in,
                              void* d_out, int out_size)
{
    const float* acts_in = (const float*)d_in[0];
    const float* ln1_w   = (const float*)d_in[4];
    const float* ln2_w   = (const float*)d_in[5];
    const float* q_w     = (const float*)d_in[6];
    const float* k_w     = (const float*)d_in[7];
    const float* v_w     = (const float*)d_in[8];
    const float* o_w     = (const float*)d_in[9];
    const float* w1      = (const float*)d_in[10];
    const float* w2      = (const float*)d_in[11];
    const int*   p_index = (const int*)d_in[3];
    float* out = (float*)d_out;

    float *p_xn, *p_q, *p_k, *p_v, *p_qt, *p_kt, *p_vt, *p_ctx, *p_acts, *p_h;
    cudaGetSymbolAddress((void**)&p_xn,  g_xn);
    cudaGetSymbolAddress((void**)&p_q,   g_q);
    cudaGetSymbolAddress((void**)&p_k,   g_k);
    cudaGetSymbolAddress((void**)&p_v,   g_v);
    cudaGetSymbolAddress((void**)&p_qt,  g_qt);
    cudaGetSymbolAddress((void**)&p_kt,  g_kt);
    cudaGetSymbolAddress((void**)&p_vt,  g_vt);
    cudaGetSymbolAddress((void**)&p_ctx, g_ctx);
    cudaGetSymbolAddress((void**)&p_acts,g_acts);
    cudaGetSymbolAddress((void**)&p_h,   g_h);

    cudaFuncSetAttribute(mm_gemm<0>, cudaFuncAttributeMaxDynamicSharedMemorySize, MMG_SMEM);
    cudaFuncSetAttribute(mm_gemm<1>, cudaFuncAttributeMaxDynamicSharedMemorySize, MMG_SMEM);
    cudaFuncSetAttribute(mm_gemm<2>, cudaFuncAttributeMaxDynamicSharedMemorySize, MMG_SMEM);

    // 1) LN1
    hx_ln<<<M_, 256>>>(acts_in, ln1_w, p_xn);

    // 2) QKV projections (tiles_m=64, tiles_n=16)
    mm_gemm<0><<<64*16, 256, MMG_SMEM>>>(M_, HID_, HID_, p_xn, q_w, nullptr, p_q, 16);
    mm_gemm<0><<<64*16, 256, MMG_SMEM>>>(M_, HID_, HID_, p_xn, k_w, nullptr, p_k, 16);
    mm_gemm<0><<<64*16, 256, MMG_SMEM>>>(M_, HID_, HID_, p_xn, v_w, nullptr, p_v, 16);

    // 3) xPos rotary (K,V) + transpose all to [B*H, S, D]
    const long nrope = (long)M_*H_*(D_/2);
    hx_rope<<<(unsigned)((nrope + 255)/256), 256>>>(p_q, p_k, p_v, p_index,
                                                    p_qt, p_kt, p_vt);

    // 4) causal flash attention
    const int attn_smem = ATTN_SMEM_FLOATS * (int)sizeof(float);
    cudaFuncSetAttribute(hx_attn, cudaFuncAttributeMaxDynamicSharedMemorySize, attn_smem);
    hx_attn<<<dim3(S_/64, B_*H_), 256, attn_smem>>>(p_qt, p_kt, p_vt, p_ctx);

    // 5) O projection + residual
    mm_gemm<1><<<64*16, 256, MMG_SMEM>>>(M_, HID_, HID_, p_ctx, o_w, acts_in, p_acts, 16);

    // 6) LN2
    hx_ln<<<M_, 256>>>(p_acts, ln2_w, p_xn);

    // 7) FFN up + exact GELU (tiles_n=64)
    mm_gemm<2><<<64*64, 256, MMG_SMEM>>>(M_, FF_, HID_, p_xn, w1, nullptr, p_h, 64);

    // 8) FFN down + residual -> output acts (K=8192)
    mm_gemm<1><<<64*16, 256, MMG_SMEM>>>(M_, HID_, FF_, p_h, w2, p_acts, out, 16);

    // 9) pass-through caches
    const long actN = (long)M_*HID_;
    if (n_in > 2 && (long)out_size >= actN + (long)in_sizes[1] + (long)in_sizes[2]) {
        cudaMemcpyAsync(out + actN, d_in[1],
                        (size_t)in_sizes[1]*sizeof(float),
                        cudaMemcpyDeviceToDevice);
        cudaMemcpyAsync(out + actN + in_sizes[1], d_in[2],
                        (size_t)in_sizes[2]*sizeof(float),
                        cudaMemcpyDeviceToDevice);
    }
}

// round 5
// speedup vs baseline: 2.0233x; 1.0763x over previous
#include <cuda_runtime.h>
#include <cuda_bf16.h>
#include <cstdint>
#include <math.h>

// ---------------- problem constants ----------------
#define B_    8
#define S_    1024
#define HID_  2048
#define H_    16
#define D_    128
#define M_    (B_*S_)      // 8192 token rows
#define FF_   (4*HID_)     // 8192

// weight plane offsets (elements)
#define OFF_Q   0L
#define OFF_K   4194304L
#define OFF_V   8388608L
#define OFF_O   12582912L
#define OFF_W1  16777216L
#define OFF_W2  33554432L
#define W_TOTAL 50331648L

// ---------------- scratch (device globals; no allocations allowed) --------
__device__ float g_q   [(size_t)M_*HID_];
__device__ float g_k   [(size_t)M_*HID_];
__device__ float g_v   [(size_t)M_*HID_];
__device__ float g_qt  [(size_t)M_*HID_];
__device__ float g_kt  [(size_t)M_*HID_];
__device__ float g_vt  [(size_t)M_*HID_];
__device__ float g_acts[(size_t)M_*HID_];
__device__ __nv_bfloat16 g_wh  [W_TOTAL];
__device__ __nv_bfloat16 g_wl  [W_TOTAL];
__device__ __nv_bfloat16 g_xnh [(size_t)M_*HID_];
__device__ __nv_bfloat16 g_xnl [(size_t)M_*HID_];
__device__ __nv_bfloat16 g_ctxh[(size_t)M_*HID_];
__device__ __nv_bfloat16 g_ctxl[(size_t)M_*HID_];
__device__ __nv_bfloat16 g_hh  [(size_t)M_*FF_];
__device__ __nv_bfloat16 g_hl  [(size_t)M_*FF_];

// ---------------- helpers ---------------------------------------------------
__device__ __forceinline__ uint32_t hx_smem_u32(const void* p) {
    uint32_t a;
    asm("{ .reg .u64 t; cvta.to.shared.u64 t, %1; cvt.u32.u64 %0, t; }" : "=r"(a) : "l"(p));
    return a;
}
#define HX_LDSM4(r, addr) \
    asm volatile("ldmatrix.sync.aligned.m8n8.x4.shared.b16 {%0,%1,%2,%3}, [%4];" \
        : "=r"((r)[0]), "=r"((r)[1]), "=r"((r)[2]), "=r"((r)[3]) : "r"(addr))

#define HX_MMA(d, a, b0, b1) \
    asm volatile("mma.sync.aligned.m16n8k16.row.col.f32.bf16.bf16.f32 " \
        "{%0,%1,%2,%3}, {%4,%5,%6,%7}, {%8,%9}, {%0,%1,%2,%3};" \
        : "+f"((d)[0]), "+f"((d)[1]), "+f"((d)[2]), "+f"((d)[3]) \
        : "r"((a)[0]), "r"((a)[1]), "r"((a)[2]), "r"((a)[3]), "r"(b0), "r"(b1))

#define HX_CPASYNC16(dst, src) \
    asm volatile("cp.async.cg.shared.global [%0], [%1], 16;" :: "r"(dst), "l"(src) : "memory")
#define HX_CPCOMMIT() asm volatile("cp.async.commit_group;" ::: "memory")

__device__ __forceinline__ uint32_t hx_pk2(float a, float b) {
    __nv_bfloat162 t; t.x = __float2bfloat16(a); t.y = __float2bfloat16(b);
    return *(uint32_t*)&t;
}
// split float4 -> hi uint2, lo uint2 (4 bf16 each)
__device__ __forceinline__ void hx_split4(float4 v, uint2& h, uint2& l) {
    __nv_bfloat16 h0 = __float2bfloat16(v.x), h1 = __float2bfloat16(v.y);
    __nv_bfloat16 h2 = __float2bfloat16(v.z), h3 = __float2bfloat16(v.w);
    __nv_bfloat162 p0; p0.x = h0; p0.y = h1;
    __nv_bfloat162 p1; p1.x = h2; p1.y = h3;
    h.x = *(uint32_t*)&p0; h.y = *(uint32_t*)&p1;
    l.x = hx_pk2(v.x - __bfloat162float(h0), v.y - __bfloat162float(h1));
    l.y = hx_pk2(v.z - __bfloat162float(h2), v.w - __bfloat162float(h3));
}

// ---------------- weight pre-split ------------------------------------------
__global__ void __launch_bounds__(256) hx_wsplit(
    const float* __restrict__ qw, const float* __restrict__ kw,
    const float* __restrict__ vw, const float* __restrict__ ow,
    const float* __restrict__ w1, const float* __restrict__ w2,
    __nv_bfloat16* __restrict__ wh, __nv_bfloat16* __restrict__ wl)
{
    const long stride = (long)gridDim.x * blockDim.x;
    for (long i = (long)blockIdx.x * blockDim.x + threadIdx.x;
         i * 4 < W_TOTAL; i += stride) {
        const long e = i * 4;
        const float* src; long off;
        if (e < OFF_W1) {
            const int m = (int)(e >> 22);
            src = (m == 0) ? qw : (m == 1) ? kw : (m == 2) ? vw : ow;
            off = e & 4194303L;
        } else if (e < OFF_W2) { src = w1; off = e - OFF_W1; }
        else                   { src = w2; off = e - OFF_W2; }
        float4 v = *(const float4*)(src + off);
        uint2 h, l;
        hx_split4(v, h, l);
        *(uint2*)(wh + e) = h;
        *(uint2*)(wl + e) = l;
    }
}

// ---------------- split-bf16 tensor-core GEMM v2 (cp.async pipeline) --------
// C[M,N] = A[M,K] @ B[N,K]^T. Operands pre-split hi/lo bf16 planes, K-major.
// CTA 128x128, K-chunk 64, 3 stages, 8 warps (2m x 4n), warp tile 64x32.
// Stage: Ah/Al/Bh/Bl planes, 128 rows x 144B (128B data + 16B pad).
// EPI: 0 = none (fp32 C), 1 = +Res (fp32 C), 2 = exact gelu -> bf16 hi/lo planes
#define MM2_PLANE   18432
#define MM2_STAGE   (4*MM2_PLANE)     // 73728
#define MM2_SMEM    (3*MM2_STAGE)     // 221184

template<int EPI, bool QKV>
__global__ void __launch_bounds__(256, 1) mm2(
    int M, int N, int K,
    const __nv_bfloat16* __restrict__ Ah, const __nv_bfloat16* __restrict__ Al,
    const __nv_bfloat16* __restrict__ Bh, const __nv_bfloat16* __restrict__ Bl,
    const float* __restrict__ Res,
    float* __restrict__ C0, float* __restrict__ C1, float* __restrict__ C2,
    __nv_bfloat16* __restrict__ Chh, __nv_bfloat16* __restrict__ Chl,
    int tiles_n)
{
    extern __shared__ char smc[];
    const uint32_t smb = hx_smem_u32(smc);
    const int tid  = threadIdx.x;
    const int lane = tid & 31;
    const int warp = tid >> 5;
    const int wm = warp & 1;
    const int wn = warp >> 1;

    // supertile raster: 16 m-tiles per band
    const int SUPER = 16;
    const int per  = SUPER * tiles_n;
    const int band = blockIdx.x / per;
    const int rem  = blockIdx.x % per;
    const int mt  = band * SUPER + (rem % SUPER);
    int ntg = rem / SUPER;

    int sel = 0;
    if (QKV) { sel = ntg >> 4; ntg &= 15; }
    const int nt = ntg;

    const long boff = QKV ? (long)sel * 4194304L : 0L;
    const __nv_bfloat16* pAh = Ah + (long)mt * 128 * K;
    const __nv_bfloat16* pAl = Al + (long)mt * 128 * K;
    const __nv_bfloat16* pBh = Bh + boff + (long)nt * 128 * K;
    const __nv_bfloat16* pBl = Bl + boff + (long)nt * 128 * K;
    float* Cw = QKV ? (sel == 0 ? C0 : sel == 1 ? C1 : C2) : C0;

    float acc[4][4][4];
#pragma unroll
    for (int i = 0; i < 4; i++)
#pragma unroll
        for (int j = 0; j < 4; j++)
#pragma unroll
            for (int r = 0; r < 4; r++) acc[i][j][r] = 0.f;

    const __nv_bfloat16* plp[4] = { pAh, pAl, pBh, pBl };

    const int lr = tid >> 3;   // 0..31 — wait, 256 threads: op mapping below
    (void)lr;

    auto issue_chunk = [&](int c, int st) {
        const uint32_t sb = smb + st * MM2_STAGE;
#pragma unroll
        for (int pl = 0; pl < 4; pl++) {
#pragma unroll
            for (int q = 0; q < 4; q++) {
                const int op = tid + q * 256;        // 0..1023
                const int r = op >> 3;               // 0..127
                const int s = op & 7;                // 16B segment
                const __nv_bfloat16* src = plp[pl] + (long)r * K + c * 64 + s * 8;
                const uint32_t dst = sb + pl * MM2_PLANE + r * 144 + s * 16;
                HX_CPASYNC16(dst, src);
            }
        }
        HX_CPCOMMIT();
    };

    const int nch = K / 64;
    issue_chunk(0, 0);
    issue_chunk(1, 1);

    for (int c = 0; c < nch; c++) {
        const int st = c % 3;
        if (c + 1 < nch) { asm volatile("cp.async.wait_group 1;" ::: "memory"); }
        else             { asm volatile("cp.async.wait_group 0;" ::: "memory"); }
        __syncthreads();
        if (c + 2 < nch) issue_chunk(c + 2, (c + 2) % 3);

        const uint32_t stb = smb + st * MM2_STAGE;
#pragma unroll
        for (int ks = 0; ks < 4; ks++) {
            const uint32_t colb = ks * 32 + (lane >> 4) * 16;
            uint32_t ah[4][4], al[4][4], bh[2][4], bl[2][4];
#pragma unroll
            for (int im = 0; im < 4; im++) {
                const uint32_t row = wm * 64 + im * 16 + (lane & 15);
                const uint32_t ad = stb + row * 144 + colb;
                HX_LDSM4(ah[im], ad);
                HX_LDSM4(al[im], ad + MM2_PLANE);
            }
#pragma unroll
            for (int ib = 0; ib < 2; ib++) {
                const uint32_t row = wn * 32 + ib * 16 + (lane & 15);
                const uint32_t bd = stb + 2 * MM2_PLANE + row * 144 + colb;
                HX_LDSM4(bh[ib], bd);
                HX_LDSM4(bl[ib], bd + MM2_PLANE);
            }
#pragma unroll
            for (int im = 0; im < 4; im++)
#pragma unroll
                for (int j = 0; j < 4; j++) {
                    const int ib = j >> 1, t = j & 1;
                    HX_MMA(acc[im][j], ah[im], bh[ib][t], bh[ib][t+2]); // hh
                    HX_MMA(acc[im][j], ah[im], bl[ib][t], bl[ib][t+2]); // hl
                    HX_MMA(acc[im][j], al[im], bh[ib][t], bh[ib][t+2]); // lh
                }
        }
    }

    // ---- epilogue ----
#pragma unroll
    for (int im = 0; im < 4; im++)
#pragma unroll
        for (int j = 0; j < 4; j++) {
            const long row0 = (long)mt * 128 + wm * 64 + im * 16 + (lane >> 2);
            const long col  = (long)nt * 128 + wn * 32 + j * 8 + (lane & 3) * 2;
            const long o0 = row0 * N + col;
            const long o1 = (row0 + 8) * N + col;
            float2 v0 = { acc[im][j][0], acc[im][j][1] };
            float2 v1 = { acc[im][j][2], acc[im][j][3] };
            if (EPI == 2) {
                v0.x = 0.5f*v0.x*(1.0f + erff(v0.x*0.70710678118654752f));
                v0.y = 0.5f*v0.y*(1.0f + erff(v0.y*0.70710678118654752f));
                v1.x = 0.5f*v1.x*(1.0f + erff(v1.x*0.70710678118654752f));
                v1.y = 0.5f*v1.y*(1.0f + erff(v1.y*0.70710678118654752f));
                __nv_bfloat16 h0 = __float2bfloat16(v0.x), h1 = __float2bfloat16(v0.y);
                __nv_bfloat16 h2 = __float2bfloat16(v1.x), h3 = __float2bfloat16(v1.y);
                __nv_bfloat162 ph0; ph0.x = h0; ph0.y = h1;
                __nv_bfloat162 ph1; ph1.x = h2; ph1.y = h3;
                *(__nv_bfloat162*)(Chh + o0) = ph0;
                *(__nv_bfloat162*)(Chh + o1) = ph1;
                __nv_bfloat162 pl0, pl1;
                pl0.x = __float2bfloat16(v0.x - __bfloat162float(h0));
                pl0.y = __float2bfloat16(v0.y - __bfloat162float(h1));
                pl1.x = __float2bfloat16(v1.x - __bfloat162float(h2));
                pl1.y = __float2bfloat16(v1.y - __bfloat162float(h3));
                *(__nv_bfloat162*)(Chl + o0) = pl0;
                *(__nv_bfloat162*)(Chl + o1) = pl1;
            } else {
                if (EPI == 1) {
                    const float2 r0 = *(const float2*)(Res + o0);
                    const float2 r1 = *(const float2*)(Res + o1);
                    v0.x += r0.x; v0.y += r0.y; v1.x += r1.x; v1.y += r1.y;
                }
                *(float2*)(Cw + o0) = v0;
                *(float2*)(Cw + o1) = v1;
            }
        }
}

// ---------------- LayerNorm -> hi/lo bf16 planes ----------------------------
__global__ void __launch_bounds__(256) hx_ln(const float* __restrict__ x,
                                             const float* __restrict__ w,
                                             __nv_bfloat16* __restrict__ outh,
                                             __nv_bfloat16* __restrict__ outl)
{
    const int row = blockIdx.x;
    const int tid = threadIdx.x;
    const float4* xr = (const float4*)(x + (long)row*HID_);
    float4 a = xr[tid];
    float4 b = xr[tid + 256];
    float s  = a.x+a.y+a.z+a.w + b.x+b.y+b.z+b.w;
    float s2 = a.x*a.x+a.y*a.y+a.z*a.z+a.w*a.w
             + b.x*b.x+b.y*b.y+b.z*b.z+b.w*b.w;
#pragma unroll
    for (int o = 16; o; o >>= 1) {
        s  += __shfl_xor_sync(0xffffffffu, s,  o);
        s2 += __shfl_xor_sync(0xffffffffu, s2, o);
    }
    __shared__ float sh[16];
    if ((tid & 31) == 0) { sh[tid >> 5] = s; sh[(tid >> 5) + 8] = s2; }
    __syncthreads();
    float ts = 0.f, ts2 = 0.f;
#pragma unroll
    for (int i = 0; i < 8; i++) { ts += sh[i]; ts2 += sh[i + 8]; }
    const float mean = ts * (1.0f/HID_);
    const float var  = ts2 * (1.0f/HID_) - mean*mean;
    const float rstd = rsqrtf(var + 1e-5f);

    const float4* wr = (const float4*)w;
    float4 w0 = wr[tid], w1v = wr[tid + 256];
    float4 o0, o1;
    o0.x = (a.x-mean)*rstd*w0.x;  o0.y = (a.y-mean)*rstd*w0.y;
    o0.z = (a.z-mean)*rstd*w0.z;  o0.w = (a.w-mean)*rstd*w0.w;
    o1.x = (b.x-mean)*rstd*w1v.x; o1.y = (b.y-mean)*rstd*w1v.y;
    o1.z = (b.z-mean)*rstd*w1v.z; o1.w = (b.w-mean)*rstd*w1v.w;

    uint2 h, l;
    hx_split4(o0, h, l);
    *(uint2*)(outh + (long)row*HID_ + tid*4) = h;
    *(uint2*)(outl + (long)row*HID_ + tid*4) = l;
    hx_split4(o1, h, l);
    *(uint2*)(outh + (long)row*HID_ + (tid+256)*4) = h;
    *(uint2*)(outl + (long)row*HID_ + (tid+256)*4) = l;
}

// ---------------- xPos rotary on K,V + transpose Q/K/V to [B*H,S,D] --------
__global__ void hx_rope(const float* __restrict__ q, const float* __restrict__ k,
                        const float* __restrict__ v, const int* __restrict__ pidx,
                        float* __restrict__ qt, float* __restrict__ kt,
                        float* __restrict__ vt)
{
    const long gid = (long)blockIdx.x * blockDim.x + threadIdx.x;
    const long total = (long)M_ * H_ * (D_/2);
    if (gid >= total) return;
    const int  i  = (int)(gid & 63);
    const int  h  = (int)((gid >> 6) & (H_-1));
    const long bs = gid >> 10;
    const int  s  = (int)(bs & (S_-1));
    const int  b  = (int)(bs >> 10);

    const long in_off  = bs*HID_ + h*D_ + 2*i;
    const long out_off = (((long)(b*H_ + h))*S_ + s)*D_ + 2*i;

    float2 qq = *(const float2*)(q + in_off);
    float2 kk = *(const float2*)(k + in_off);
    float2 vv = *(const float2*)(v + in_off);

    const float seq = (float)(pidx[0] + s - (S_/2)) * (1.0f/512.0f);
    const float df  = 2.0f * (float)(i + 1);
    const float theta = expf(-(df * (1.0f/(float)D_)) * 9.210340371976184f);
    float sn, c;
    sincosf(seq * theta, &sn, &c);
    const float zeta = (df*(1.0f/64.0f) + 51.2f) * (1.0f/52.2f);
    const float t  = powf(zeta, seq);
    const float it = 1.0f / t;

    float2 ko, vo;
    ko.x = (kk.x*c - kk.y*sn)*t;   ko.y = (kk.y*c + kk.x*sn)*t;
    vo.x = (vv.x*c - vv.y*sn)*it;  vo.y = (vv.y*c + vv.x*sn)*it;

    *(float2*)(qt + out_off) = qq;
    *(float2*)(kt + out_off) = ko;
    *(float2*)(vt + out_off) = vo;
}

// ---------------- causal flash attention (fp32, BM=BN=64, D=128) -----------
#define ATTN_SMEM_FLOATS (128*65 + 128*65 + 64*65 + 64*128)
__global__ void __launch_bounds__(256) hx_attn(
    const float* __restrict__ qt, const float* __restrict__ kt,
    const float* __restrict__ vt,
    __nv_bfloat16* __restrict__ ctxh, __nv_bfloat16* __restrict__ ctxl)
{
    extern __shared__ float smf[];
    float* Qst = smf;
    float* Kst = Qst + 128*65;
    float* Pst = Kst + 128*65;
    float* Vs  = Pst + 64*65;

    const int qtile = blockIdx.x;
    const int bh    = blockIdx.y;
    const int b = bh >> 4, h = bh & 15;
    const float* Qg = qt + ((long)bh*S_ + qtile*64)*D_;
    const float* Kg = kt + (long)bh*S_*D_;
    const float* Vg = vt + (long)bh*S_*D_;

    const int tid = threadIdx.x;
    const int d4 = tid & 31, mr = tid >> 5;
    const int tx = tid & 15, ty = tid >> 4;

#pragma unroll
    for (int p = 0; p < 8; p++) {
        const int m = mr + p*8;
        float4 qv = *(const float4*)(Qg + m*D_ + d4*4);
        Qst[(d4*4+0)*65 + m] = qv.x;
        Qst[(d4*4+1)*65 + m] = qv.y;
        Qst[(d4*4+2)*65 + m] = qv.z;
        Qst[(d4*4+3)*65 + m] = qv.w;
    }

    float mi[4], li[4], o[4][8];
#pragma unroll
    for (int i = 0; i < 4; i++) {
        mi[i] = -INFINITY; li[i] = 0.f;
#pragma unroll
        for (int c = 0; c < 8; c++) o[i][c] = 0.f;
    }
    const float scale = 0.088388347648318447f;

    for (int j = 0; j <= qtile; j++) {
        __syncthreads();
#pragma unroll
        for (int p = 0; p < 8; p++) {
            const int n = mr + p*8;
            float4 kv = *(const float4*)(Kg + (long)(j*64 + n)*D_ + d4*4);
            Kst[(d4*4+0)*65 + n] = kv.x;
            Kst[(d4*4+1)*65 + n] = kv.y;
            Kst[(d4*4+2)*65 + n] = kv.z;
            Kst[(d4*4+3)*65 + n] = kv.w;
            float4 vv = *(const float4*)(Vg + (long)(j*64 + n)*D_ + d4*4);
            *(float4*)&Vs[n*128 + d4*4] = vv;
        }
        __syncthreads();

        float sacc[4][4];
#pragma unroll
        for (int i = 0; i < 4; i++)
#pragma unroll
            for (int jj = 0; jj < 4; jj++) sacc[i][jj] = 0.f;
        for (int d = 0; d < 128; d++) {
            float qr[4], kr[4];
#pragma unroll
            for (int i = 0; i < 4; i++)  qr[i]  = Qst[d*65 + ty*4 + i];
#pragma unroll
            for (int jj = 0; jj < 4; jj++) kr[jj] = Kst[d*65 + tx*4 + jj];
#pragma unroll
            for (int i = 0; i < 4; i++)
#pragma unroll
                for (int jj = 0; jj < 4; jj++)
                    sacc[i][jj] = fmaf(qr[i], kr[jj], sacc[i][jj]);
        }

#pragma unroll
        for (int i = 0; i < 4; i++) {
            const int mg = qtile*64 + ty*4 + i;
            float rmax = -INFINITY;
#pragma unroll
            for (int jj = 0; jj < 4; jj++) {
                const int ng = j*64 + tx*4 + jj;
                float sv = sacc[i][jj] * scale;
                sv = (ng <= mg) ? sv : -INFINITY;
                sacc[i][jj] = sv;
                rmax = fmaxf(rmax, sv);
            }
#pragma unroll
            for (int off = 8; off; off >>= 1)
                rmax = fmaxf(rmax, __shfl_xor_sync(0xffffffffu, rmax, off));
            const float mnew  = fmaxf(mi[i], rmax);
            const float alpha = expf(mi[i] - mnew);
            float rsum = 0.f;
#pragma unroll
            for (int jj = 0; jj < 4; jj++) {
                const float pv = expf(sacc[i][jj] - mnew);
                sacc[i][jj] = pv;
                rsum += pv;
            }
#pragma unroll
            for (int off = 8; off; off >>= 1)
                rsum += __shfl_xor_sync(0xffffffffu, rsum, off);
            li[i] = li[i]*alpha + rsum;
            mi[i] = mnew;
#pragma unroll
            for (int c = 0; c < 8; c++) o[i][c] *= alpha;
#pragma unroll
            for (int jj = 0; jj < 4; jj++)
                Pst[(tx*4 + jj)*65 + ty*4 + i] = sacc[i][jj];
        }
        __syncthreads();

#pragma unroll 4
        for (int n = 0; n < 64; n++) {
            float pr[4], vr[8];
#pragma unroll
            for (int i = 0; i < 4; i++) pr[i] = Pst[n*65 + ty*4 + i];
#pragma unroll
            for (int c = 0; c < 8; c++) vr[c] = Vs[n*128 + tx*8 + c];
#pragma unroll
            for (int i = 0; i < 4; i++)
#pragma unroll
                for (int c = 0; c < 8; c++)
                    o[i][c] = fmaf(pr[i], vr[c], o[i][c]);
        }
    }

#pragma unroll
    for (int i = 0; i < 4; i++) {
        const float inv = 1.0f / li[i];
        const int sq = qtile*64 + ty*4 + i;
        const long off = ((long)(b*S_ + sq))*HID_ + h*D_ + tx*8;
        float4 v0 = { o[i][0]*inv, o[i][1]*inv, o[i][2]*inv, o[i][3]*inv };
        float4 v1 = { o[i][4]*inv, o[i][5]*inv, o[i][6]*inv, o[i][7]*inv };
        uint2 h0, l0, h1, l1;
        hx_split4(v0, h0, l0);
        hx_split4(v1, h1, l1);
        uint4 hv; hv.x = h0.x; hv.y = h0.y; hv.z = h1.x; hv.w = h1.y;
        uint4 lv; lv.x = l0.x; lv.y = l0.y; lv.z = l1.x; lv.w = l1.y;
        *(uint4*)(ctxh + off) = hv;
        *(uint4*)(ctxl + off) = lv;
    }
}

// ---------------- launch ----------------------------------------------------
extern "C" void kernel_launch(void* const* d_in, const int* in_sizes, int n_in,
                              void* d_out, int out_size)
{
    const float* acts_in = (const float*)d_in[0];
    const float* ln1_w   = (const float*)d_in[4];
    const float* ln2_w   = (const float*)d_in[5];
    const float* q_w     = (const float*)d_in[6];
    const float* k_w     = (const float*)d_in[7];
    const float* v_w     = (const float*)d_in[8];
    const float* o_w     = (const float*)d_in[9];
    const float* w1      = (const float*)d_in[10];
    const float* w2      = (const float*)d_in[11];
    const int*   p_index = (const int*)d_in[3];
    float* out = (float*)d_out;

    float *p_q, *p_k, *p_v, *p_qt, *p_kt, *p_vt, *p_acts;
    __nv_bfloat16 *p_wh, *p_wl, *p_xnh, *p_xnl, *p_ctxh, *p_ctxl, *p_hh, *p_hl;
    cudaGetSymbolAddress((void**)&p_q,    g_q);
    cudaGetSymbolAddress((void**)&p_k,    g_k);
    cudaGetSymbolAddress((void**)&p_v,    g_v);
    cudaGetSymbolAddress((void**)&p_qt,   g_qt);
    cudaGetSymbolAddress((void**)&p_kt,   g_kt);
    cudaGetSymbolAddress((void**)&p_vt,   g_vt);
    cudaGetSymbolAddress((void**)&p_acts, g_acts);
    cudaGetSymbolAddress((void**)&p_wh,   g_wh);
    cudaGetSymbolAddress((void**)&p_wl,   g_wl);
    cudaGetSymbolAddress((void**)&p_xnh,  g_xnh);
    cudaGetSymbolAddress((void**)&p_xnl,  g_xnl);
    cudaGetSymbolAddress((void**)&p_ctxh, g_ctxh);
    cudaGetSymbolAddress((void**)&p_ctxl, g_ctxl);
    cudaGetSymbolAddress((void**)&p_hh,   g_hh);
    cudaGetSymbolAddress((void**)&p_hl,   g_hl);

    cudaFuncSetAttribute(mm2<0,true>,  cudaFuncAttributeMaxDynamicSharedMemorySize, MM2_SMEM);
    cudaFuncSetAttribute(mm2<1,false>, cudaFuncAttributeMaxDynamicSharedMemorySize, MM2_SMEM);
    cudaFuncSetAttribute(mm2<2,false>, cudaFuncAttributeMaxDynamicSharedMemorySize, MM2_SMEM);

    // 0) weight pre-split (independent of LN)
    hx_wsplit<<<4096, 256>>>(q_w, k_w, v_w, o_w, w1, w2, p_wh, p_wl);

    // 1) LN1 -> xn hi/lo planes
    hx_ln<<<M_, 256>>>(acts_in, ln1_w, p_xnh, p_xnl);

    // 2) fused QKV projection (48 n-tiles)
    mm2<0,true><<<64*48, 256, MM2_SMEM>>>(M_, HID_, HID_,
        p_xnh, p_xnl, p_wh, p_wl, nullptr, p_q, p_k, p_v, nullptr, nullptr, 48);

    // 3) xPos rotary (K,V) + transpose
    const long nrope = (long)M_*H_*(D_/2);
    hx_rope<<<(unsigned)((nrope + 255)/256), 256>>>(p_q, p_k, p_v, p_index,
                                                    p_qt, p_kt, p_vt);

    // 4) causal flash attention -> ctx hi/lo planes
    const int attn_smem = ATTN_SMEM_FLOATS * (int)sizeof(float);
    cudaFuncSetAttribute(hx_attn, cudaFuncAttributeMaxDynamicSharedMemorySize, attn_smem);
    hx_attn<<<dim3(S_/64, B_*H_), 256, attn_smem>>>(p_qt, p_kt, p_vt, p_ctxh, p_ctxl);

    // 5) O projection + residual -> acts fp32
    mm2<1,false><<<64*16, 256, MM2_SMEM>>>(M_, HID_, HID_,
        p_ctxh, p_ctxl, p_wh + OFF_O, p_wl + OFF_O, acts_in,
        p_acts, nullptr, nullptr, nullptr, nullptr, 16);

    // 6) LN2 -> xn hi/lo planes (reuse)
    hx_ln<<<M_, 256>>>(p_acts, ln2_w, p_xnh, p_xnl);

    // 7) FFN up + exact GELU -> h hi/lo planes
    mm2<2,false><<<64*64, 256, MM2_SMEM>>>(M_, FF_, HID_,
        p_xnh, p_xnl, p_wh + OFF_W1, p_wl + OFF_W1, nullptr,
        nullptr, nullptr, nullptr, p_hh, p_hl, 64);

    // 8) FFN down + residual -> output acts
    mm2<1,false><<<64*16, 256, MM2_SMEM>>>(M_, HID_, FF_,
        p_hh, p_hl, p_wh + OFF_W2, p_wl + OFF_W2, p_acts,
        out, nullptr, nullptr, nullptr, nullptr, 16);

    // 9) pass-through caches
    const long actN = (long)M_*HID_;
    if (n_in > 2 && (long)out_size >= actN + (long)in_sizes[1] + (long)in_sizes[2]) {
        cudaMemcpyAsync(out + actN, d_in[1],
                        (size_t)in_sizes[1]*sizeof(float),
                        cudaMemcpyDeviceToDevice);
        cudaMemcpyAsync(out + actN + in_sizes[1], d_in[2],
                        (size_t)in_sizes[2]*sizeof(float),
                        cudaMemcpyDeviceToDevice);
    }
}